// round 12
// baseline (speedup 1.0000x reference)
#include <cuda_runtime.h>
#include <math.h>

#define NB 8
#define NL 12
#define NS 1023
#define NS1 1024
#define NE 768
#define NH 12
#define ND 64
#define NV 50257
#define NFF 3072
#define NE3 2304

#define PDL_PROLOG  do { \
    asm volatile("griddepcontrol.launch_dependents;"); \
    asm volatile("griddepcontrol.wait;"); \
} while(0)

// ---------------- scratch (device globals) -------------------------------------
__device__ __align__(16) float g_states[NB*NE];
__device__ __align__(16) float g_qkv[NB*NE3];
__device__ __align__(16) float g_ctx[NB*NE];
__device__ __align__(16) float g_hbuf[NB*NFF];
__device__ __align__(16) float g_scores[NB*NH*NS1];
__device__ __align__(16) float g_logits[NB*NV];
__device__ int g_lp[NB];

// ---------------- embedding + last-position; zero qkv & ctx --------------------
__global__ void embed_kernel(const int* __restrict__ ids, const int* __restrict__ mask,
                             const float* __restrict__ wte, const float* __restrict__ wpe){
    PDL_PROLOG;
    int b = blockIdx.x, tid = threadIdx.x;
    __shared__ int s_lp;
    if (tid < 32){
        int best = -1;
        for (int s = tid; s < NS1; s += 32)
            if (mask[b*NS1 + s] != 0) best = (s > best) ? s : best;
        for (int o = 16; o; o >>= 1){
            int ot = __shfl_xor_sync(0xffffffffu, best, o);
            best = (ot > best) ? ot : best;
        }
        if (tid == 0){ s_lp = best; g_lp[b] = best; }
    }
    __syncthreads();
    int lp  = s_lp;
    int tok = ids[b*NS1 + lp];
    for (int e = tid; e < NE; e += blockDim.x)
        g_states[b*NE + e] = wte[(size_t)tok*NE + e] + wpe[(size_t)lp*NE + e];
    int g = b*256 + tid;
    for (int i = g; i < NB*NE3; i += NB*256) g_qkv[i] = 0.f;
    for (int i = g; i < NB*NE;  i += NB*256) g_ctx[i] = 0.f;
}

// ---------------- bulk kv -> new_kv copy (side stream; independent of layers) --
// warp per row over all NL*2*NB*NS1 rows; skips lp rows (attn_kv writes those).
__global__ void kvcopy_kernel(const float* __restrict__ kv, float* __restrict__ nkv){
    int warp = threadIdx.x >> 5, lane = threadIdx.x & 31;
    long long r = (long long)blockIdx.x*8 + warp;
    int s = (int)(r & (NS1-1));
    long long t = r >> 10;                // (l*2+kvidx)*NB + b  in 0..191
    int b = (int)(t & 7);
    int lp = g_lp[b];
    if (s == lp) return;
    float* dst = nkv + r*(long long)NE;
    if (s == NS){
        float4 z = make_float4(0.f,0.f,0.f,0.f);
        #pragma unroll
        for (int c = 0; c < 6; c++)
            __stcs((float4*)(dst + c*128 + lane*4), z);
        return;
    }
    const float* src = kv + (t*(long long)NS + s)*NE;
    float4 v4[6];
    #pragma unroll
    for (int c = 0; c < 6; c++)
        v4[c] = __ldcs((const float4*)(src + c*128 + lane*4));
    #pragma unroll
    for (int c = 0; c < 6; c++)
        __stcs((float4*)(dst + c*128 + lane*4), v4[c]);
}

// ---------------- GEMV with fused redundant layernorm of g_states --------------
template<int CH>
__global__ void gemv_ln_kernel(const float* __restrict__ lnw, const float* __restrict__ lnb,
                               const float* __restrict__ W, const float* __restrict__ bias,
                               float* __restrict__ out, int N){
    PDL_PROLOG;
    __shared__ __align__(16) float xs[8*CH];
    int tid = threadIdx.x, warp = tid >> 5, lane = tid & 31;
    int e0 = blockIdx.y * CH;
    {   // LN of row `warp`
        const float* x = g_states + warp*NE;
        float s = 0.f;
        for (int i = lane; i < NE; i += 32) s += x[i];
        #pragma unroll
        for (int o = 16; o; o >>= 1) s += __shfl_xor_sync(0xffffffffu, s, o);
        float mean = s*(1.0f/NE);
        float v = 0.f;
        for (int i = lane; i < NE; i += 32){ float d = x[i]-mean; v += d*d; }
        #pragma unroll
        for (int o = 16; o; o >>= 1) v += __shfl_xor_sync(0xffffffffu, v, o);
        float rs = rsqrtf(v*(1.0f/NE) + 1e-5f);
        for (int i = lane; i < CH; i += 32){
            int e = e0 + i;
            xs[warp*CH + i] = (x[e]-mean)*rs*lnw[e] + lnb[e];
        }
    }
    __syncthreads();
    int j = (blockIdx.x*256 + tid)*4;
    if (j >= N) return;
    float4 acc[8];
    #pragma unroll
    for (int b2 = 0; b2 < 8; b2++) acc[b2] = make_float4(0.f,0.f,0.f,0.f);
    const float* Wp = W + (size_t)e0*N + j;
    #pragma unroll
    for (int e = 0; e < CH; e++){
        float4 w4 = *(const float4*)(Wp + (size_t)e*N);
        #pragma unroll
        for (int b2 = 0; b2 < 8; b2++){
            float xv = xs[b2*CH + e];
            acc[b2].x = fmaf(xv,w4.x,acc[b2].x); acc[b2].y = fmaf(xv,w4.y,acc[b2].y);
            acc[b2].z = fmaf(xv,w4.z,acc[b2].z); acc[b2].w = fmaf(xv,w4.w,acc[b2].w);
        }
    }
    if (blockIdx.y == 0){
        float4 bv = *(const float4*)(bias + j);
        #pragma unroll
        for (int b2 = 0; b2 < 8; b2++){
            acc[b2].x += bv.x; acc[b2].y += bv.y; acc[b2].z += bv.z; acc[b2].w += bv.w;
        }
    }
    #pragma unroll
    for (int b2 = 0; b2 < 8; b2++){
        float* p = out + (size_t)b2*N + j;
        atomicAdd(p+0,acc[b2].x); atomicAdd(p+1,acc[b2].y);
        atomicAdd(p+2,acc[b2].z); atomicAdd(p+3,acc[b2].w);
    }
}

// ---------------- plain GEMV (optional gelu) + optional buffer zeroing ---------
template<int CH, int DOGELU>
__global__ void gemv_kernel(const float* __restrict__ x, const float* __restrict__ W,
                            const float* __restrict__ bias, float* __restrict__ out,
                            int M, int N, float* zbuf, int zn){
    PDL_PROLOG;
    __shared__ __align__(16) float xs[8*CH];
    int tid = threadIdx.x;
    int e0 = blockIdx.y * CH;
    if (zbuf){
        int nb = gridDim.x*gridDim.y;
        for (int i = (blockIdx.y*gridDim.x + blockIdx.x)*256 + tid; i < zn; i += nb*256)
            zbuf[i] = 0.f;
    }
    for (int i = tid; i < 8*CH; i += 256){
        int b2 = i / CH, e = i - b2*CH;
        float v = x[b2*M + e0 + e];
        if (DOGELU) v = 0.5f*v*(1.0f + erff(v*0.70710678118654752f));
        xs[b2*CH + e] = v;
    }
    __syncthreads();
    int j = (blockIdx.x*256 + tid)*4;
    if (j >= N) return;
    float4 acc[8];
    #pragma unroll
    for (int b2 = 0; b2 < 8; b2++) acc[b2] = make_float4(0.f,0.f,0.f,0.f);
    const float* Wp = W + (size_t)e0*N + j;
    #pragma unroll
    for (int e = 0; e < CH; e++){
        float4 w4 = *(const float4*)(Wp + (size_t)e*N);
        #pragma unroll
        for (int b2 = 0; b2 < 8; b2++){
            float xv = xs[b2*CH + e];
            acc[b2].x = fmaf(xv,w4.x,acc[b2].x); acc[b2].y = fmaf(xv,w4.y,acc[b2].y);
            acc[b2].z = fmaf(xv,w4.z,acc[b2].z); acc[b2].w = fmaf(xv,w4.w,acc[b2].w);
        }
    }
    if (blockIdx.y == 0){
        float4 bv = *(const float4*)(bias + j);
        #pragma unroll
        for (int b2 = 0; b2 < 8; b2++){
            acc[b2].x += bv.x; acc[b2].y += bv.y; acc[b2].z += bv.z; acc[b2].w += bv.w;
        }
    }
    #pragma unroll
    for (int b2 = 0; b2 < 8; b2++){
        float* p = out + (size_t)b2*N + j;
        atomicAdd(p+0,acc[b2].x); atomicAdd(p+1,acc[b2].y);
        atomicAdd(p+2,acc[b2].z); atomicAdd(p+3,acc[b2].w);
    }
}

// ---------------- attention scores (K read only) + lp-row K/V write; zero hbuf --
__global__ void attn_kv_kernel(const float* __restrict__ kv, const float* __restrict__ abias,
                               const int* __restrict__ mask, float* __restrict__ nkv, int l){
    PDL_PROLOG;
    int b = blockIdx.x, sc = blockIdx.y;
    int tid = threadIdx.x, warp = tid >> 5, lane = tid & 31;
    {
        for (int i = (b*128 + sc)*256 + tid; i < NB*NFF; i += NB*128*256) g_hbuf[i] = 0.f;
    }
    __shared__ __align__(16) float qs[NE];
    for (int i = tid; i < NE; i += 256) qs[i] = g_qkv[b*NE3 + i];
    __syncthreads();
    int lp = g_lp[b];
    const float* kc = kv + ((size_t)(l*2+0)*NB + b)*(size_t)NS*NE;
    int s = sc*8 + warp;
    bool isnew = (s == lp);
    bool iszero = (s == NS) && !isnew;
    const float* ksrc = isnew ? (g_qkv + b*NE3 + NE) : (kc + (size_t)s*NE);
    float4 k4[6];
    #pragma unroll
    for (int c = 0; c < 6; c++){
        int e = c*128 + lane*4;
        k4[c] = iszero ? make_float4(0.f,0.f,0.f,0.f) : *(const float4*)(ksrc + e);
    }
    if (isnew && nkv){   // write only the new row; bulk copy handles the rest
        float* ko = nkv + ((size_t)(l*2+0)*NB + b)*(size_t)NS1*NE + (size_t)s*NE;
        float* vo = nkv + ((size_t)(l*2+1)*NB + b)*(size_t)NS1*NE + (size_t)s*NE;
        const float* vsrc = g_qkv + b*NE3 + 2*NE;
        #pragma unroll
        for (int c = 0; c < 6; c++){
            int e = c*128 + lane*4;
            __stcs((float4*)(ko + e), k4[c]);
            __stcs((float4*)(vo + e), *(const float4*)(vsrc + e));
        }
    }
    float part[6];
    #pragma unroll
    for (int c = 0; c < 6; c++){
        int e = c*128 + lane*4;
        part[c] = k4[c].x*qs[e] + k4[c].y*qs[e+1] + k4[c].z*qs[e+2] + k4[c].w*qs[e+3];
    }
    #pragma unroll
    for (int c = 0; c < 6; c++){
        float p = part[c];
        p += __shfl_xor_sync(0xffffffffu, p, 8);
        p += __shfl_xor_sync(0xffffffffu, p, 4);
        p += __shfl_xor_sync(0xffffffffu, p, 2);
        p += __shfl_xor_sync(0xffffffffu, p, 1);
        part[c] = p;
    }
    if ((lane & 15) == 0){
        int hb = lane >> 4;
        bool msk = (mask[b*NS1 + s] == 0);
        float ab = abias[s];
        #pragma unroll
        for (int c = 0; c < 6; c++){
            int h = 2*c + hb;
            g_scores[(b*NH + h)*NS1 + s] = msk ? -1e9f : (part[c]*0.125f + ab);
        }
    }
}

// ---------------- softmax + weighted-V (V from original kv + g_qkv lp row) ------
// grid (B, H, 16) x 256: block = one (b,h) x 64-row chunk; redundant softmax.
__global__ void attn_sv_kernel(const float* __restrict__ kv, int l){
    PDL_PROLOG;
    int b = blockIdx.x, h = blockIdx.y, ck = blockIdx.z;
    int tid = threadIdx.x;
    __shared__ float sm[NS1];
    __shared__ float red[8];
    const float* sr = g_scores + ((size_t)b*NH + h)*NS1;
    float v[4]; float m = -1e30f;
    #pragma unroll
    for (int k = 0; k < 4; k++){ v[k] = sr[tid + k*256]; m = fmaxf(m, v[k]); }
    #pragma unroll
    for (int o = 16; o; o >>= 1) m = fmaxf(m, __shfl_xor_sync(0xffffffffu, m, o));
    if ((tid & 31) == 0) red[tid >> 5] = m;
    __syncthreads();
    m = red[0];
    #pragma unroll
    for (int w2 = 1; w2 < 8; w2++) m = fmaxf(m, red[w2]);
    float ssum = 0.f;
    #pragma unroll
    for (int k = 0; k < 4; k++){ v[k] = expf(v[k] - m); ssum += v[k]; }
    #pragma unroll
    for (int o = 16; o; o >>= 1) ssum += __shfl_xor_sync(0xffffffffu, ssum, o);
    __syncthreads();
    if ((tid & 31) == 0) red[tid >> 5] = ssum;
    __syncthreads();
    float tot = red[0];
    #pragma unroll
    for (int w2 = 1; w2 < 8; w2++) tot += red[w2];
    float inv = 1.0f/tot;
    #pragma unroll
    for (int k = 0; k < 4; k++) sm[tid + k*256] = v[k]*inv;
    __syncthreads();
    int col = tid & 63, rp = tid >> 6;          // rp in 0..3
    int lp = g_lp[b];
    const float* vc = kv + ((size_t)(l*2+1)*NB + b)*(size_t)NS*NE;
    float newv = g_qkv[b*NE3 + 2*NE + h*ND + col];
    float acc = 0.f;
    #pragma unroll
    for (int i = 0; i < 16; i++){
        int s = ck*64 + i*4 + rp;
        float vv;
        if (s == lp) vv = newv;
        else if (s == NS) vv = 0.f;
        else vv = vc[(size_t)s*NE + h*ND + col];
        acc = fmaf(sm[s], vv, acc);
    }
    __shared__ float cacc[256];
    cacc[tid] = acc; __syncthreads();
    if (tid < 64)
        atomicAdd(&g_ctx[b*NE + h*ND + tid],
                  cacc[tid] + cacc[tid+64] + cacc[tid+128] + cacc[tid+192]);
}

// ---------------- lm head with fused final layernorm ---------------------------
__global__ void lm_kernel(const float* __restrict__ wte, const float* __restrict__ lnfw,
                          const float* __restrict__ lnfb){
    PDL_PROLOG;
    __shared__ __align__(16) float xs[NB*NE];
    int tid = threadIdx.x;
    int warp = tid >> 5, lane = tid & 31;
    {   // redundant LN of row `warp` (8 warps = 8 batch rows)
        const float* x = g_states + warp*NE;
        float s = 0.f;
        for (int i = lane; i < NE; i += 32) s += x[i];
        #pragma unroll
        for (int o = 16; o; o >>= 1) s += __shfl_xor_sync(0xffffffffu, s, o);
        float mean = s*(1.0f/NE);
        float v = 0.f;
        for (int i = lane; i < NE; i += 32){ float d = x[i]-mean; v += d*d; }
        #pragma unroll
        for (int o = 16; o; o >>= 1) v += __shfl_xor_sync(0xffffffffu, v, o);
        float rs = rsqrtf(v*(1.0f/NE) + 1e-5f);
        for (int i = lane; i < NE; i += 32)
            xs[warp*NE + i] = (x[i]-mean)*rs*lnfw[i] + lnfb[i];
    }
    __syncthreads();
    long long t0 = (long long)blockIdx.x*16 + warp*2;
    if (t0 >= NV) return;
    bool has1 = (t0 + 1 < NV);
    const float* r0 = wte + (size_t)t0*NE;
    const float* r1 = has1 ? wte + (size_t)(t0+1)*NE : r0;
    float acc[16];
    #pragma unroll
    for (int i = 0; i < 16; i++) acc[i] = 0.f;
    #pragma unroll
    for (int c = 0; c < 6; c++){
        int e = c*128 + lane*4;
        float4 w0 = *(const float4*)(r0 + e);
        float4 w1 = *(const float4*)(r1 + e);
        #pragma unroll
        for (int b2 = 0; b2 < 8; b2++){
            float4 x4 = *(const float4*)&xs[b2*NE + e];
            acc[b2]   = fmaf(w0.x,x4.x, fmaf(w0.y,x4.y, fmaf(w0.z,x4.z, fmaf(w0.w,x4.w, acc[b2]))));
            acc[8+b2] = fmaf(w1.x,x4.x, fmaf(w1.y,x4.y, fmaf(w1.z,x4.z, fmaf(w1.w,x4.w, acc[8+b2]))));
        }
    }
    #pragma unroll
    for (int i = 0; i < 16; i++){
        float p = acc[i];
        p += __shfl_xor_sync(0xffffffffu, p, 16);
        p += __shfl_xor_sync(0xffffffffu, p, 8);
        p += __shfl_xor_sync(0xffffffffu, p, 4);
        p += __shfl_xor_sync(0xffffffffu, p, 2);
        p += __shfl_xor_sync(0xffffffffu, p, 1);
        acc[i] = p;
    }
    if (lane < 8){
        g_logits[(size_t)lane*NV + t0] = acc[lane];
        if (has1) g_logits[(size_t)lane*NV + t0 + 1] = acc[8 + lane];
    }
}

// ---------------- vocab softmax + argmax (ILP-4 loops) -------------------------
__global__ void finish_kernel(float* __restrict__ probs, float* __restrict__ chosen_f,
                              int* __restrict__ chosen_i){
    PDL_PROLOG;
    int b = blockIdx.x, tid = threadIdx.x;
    __shared__ float rv[1024];
    __shared__ int   ri[1024];
    const float* lg = g_logits + (size_t)b*NV;
    float m = -1e30f; int mi = 0;
    for (int t = tid; t < NV; t += 4096){
        float v0 = lg[t];
        float v1 = (t+1024 < NV) ? lg[t+1024] : -1e30f;
        float v2 = (t+2048 < NV) ? lg[t+2048] : -1e30f;
        float v3 = (t+3072 < NV) ? lg[t+3072] : -1e30f;
        if (v0 > m){ m = v0; mi = t; }
        if (v1 > m){ m = v1; mi = t+1024; }
        if (v2 > m){ m = v2; mi = t+2048; }
        if (v3 > m){ m = v3; mi = t+3072; }
    }
    rv[tid] = m; ri[tid] = mi; __syncthreads();
    for (int o = 512; o; o >>= 1){
        if (tid < o){
            if (rv[tid+o] > rv[tid] || (rv[tid+o] == rv[tid] && ri[tid+o] < ri[tid])){
                rv[tid] = rv[tid+o]; ri[tid] = ri[tid+o];
            }
        }
        __syncthreads();
    }
    float mx = rv[0]; int am = ri[0]; __syncthreads();
    float s = 0.f;
    for (int t = tid; t < NV; t += 4096){
        float v0 = lg[t];
        float v1 = (t+1024 < NV) ? lg[t+1024] : 0.f;
        float v2 = (t+2048 < NV) ? lg[t+2048] : 0.f;
        float v3 = (t+3072 < NV) ? lg[t+3072] : 0.f;
        float e0 = expf(v0-mx);
        float e1 = (t+1024 < NV) ? expf(v1-mx) : 0.f;
        float e2 = (t+2048 < NV) ? expf(v2-mx) : 0.f;
        float e3 = (t+3072 < NV) ? expf(v3-mx) : 0.f;
        s += (e0+e1)+(e2+e3);
        if (probs){
            probs[(size_t)b*NV + t] = e0;
            if (t+1024 < NV) probs[(size_t)b*NV + t+1024] = e1;
            if (t+2048 < NV) probs[(size_t)b*NV + t+2048] = e2;
            if (t+3072 < NV) probs[(size_t)b*NV + t+3072] = e3;
        }
    }
    rv[tid] = s; __syncthreads();
    for (int o = 512; o; o >>= 1){ if (tid < o) rv[tid] += rv[tid+o]; __syncthreads(); }
    float inv = 1.0f/rv[0];
    if (probs){
        float* pb = probs + (size_t)b*NV;
        for (int t = tid; t < NV; t += 4096){
            float p0 = pb[t];
            float p1 = (t+1024 < NV) ? pb[t+1024] : 0.f;
            float p2 = (t+2048 < NV) ? pb[t+2048] : 0.f;
            float p3 = (t+3072 < NV) ? pb[t+3072] : 0.f;
            pb[t] = p0*inv;
            if (t+1024 < NV) pb[t+1024] = p1*inv;
            if (t+2048 < NV) pb[t+2048] = p2*inv;
            if (t+3072 < NV) pb[t+3072] = p3*inv;
        }
    }
    if (tid == 0){
        if (chosen_f) chosen_f[b] = (float)am;
        if (chosen_i) chosen_i[b] = am;
    }
}

// ---------------- PDL launch helper ---------------------------------------------
template <typename... ExpTypes, typename... ActTypes>
static inline void pdl_launch(void (*kern)(ExpTypes...), dim3 grid, dim3 block,
                              ActTypes... args){
    cudaLaunchConfig_t cfg = {};
    cfg.gridDim = grid;
    cfg.blockDim = block;
    cfg.dynamicSmemBytes = 0;
    cfg.stream = 0;
    cudaLaunchAttribute at[1];
    at[0].id = cudaLaunchAttributeProgrammaticStreamSerialization;
    at[0].val.programmaticStreamSerializationAllowed = 1;
    cfg.attrs = at;
    cfg.numAttrs = 1;
    cudaLaunchKernelEx(&cfg, kern, (ExpTypes)args...);
}

// ---------------- launch --------------------------------------------------------
extern "C" void kernel_launch(void* const* d_in, const int* in_sizes, int n_in,
                              void* d_out, int out_size){
    const int*   ids  = (const int*)  d_in[0];
    const int*   mask = (const int*)  d_in[1];
    const float* kv   = (const float*)d_in[2];
    const float* wte  = (const float*)d_in[3];
    const float* wpe  = (const float*)d_in[4];
    const float* ln1w = (const float*)d_in[5];
    const float* ln1b = (const float*)d_in[6];
    const float* caw  = (const float*)d_in[7];
    const float* cab  = (const float*)d_in[8];
    const float* ab   = (const float*)d_in[9];
    const float* cpw  = (const float*)d_in[10];
    const float* cpb  = (const float*)d_in[11];
    const float* ln2w = (const float*)d_in[12];
    const float* ln2b = (const float*)d_in[13];
    const float* fcw  = (const float*)d_in[14];
    const float* fcb  = (const float*)d_in[15];
    const float* prw  = (const float*)d_in[16];
    const float* prb  = (const float*)d_in[17];
    const float* lnfw = (const float*)d_in[18];
    const float* lnfb = (const float*)d_in[19];

    float *st, *qkvp, *ctxp, *hb;
    cudaGetSymbolAddress((void**)&st,   g_states);
    cudaGetSymbolAddress((void**)&qkvp, g_qkv);
    cudaGetSymbolAddress((void**)&ctxp, g_ctx);
    cudaGetSymbolAddress((void**)&hb,   g_hbuf);

    long long nkvN  = (long long)NL*2*NB*NS1*NE;                  // 150,994,944
    long long fullN = (long long)NB + (long long)NB*NV + nkvN;    // 151,397,008
    float* outf = (float*)d_out;
    float* chosen_f = nullptr; int* chosen_i = nullptr;
    float* probs = nullptr; float* nkv = nullptr;
    long long osz = (long long)out_size;
    if (osz == fullN){ chosen_f = outf; probs = outf + NB; nkv = outf + NB + (long long)NB*NV; }
    else if (osz == nkvN){ nkv = outf; }
    else if (osz == (long long)NB*NV){ probs = outf; }
    else if (osz == (long long)NB){ chosen_i = (int*)d_out; }
    else if (osz == (long long)NB + (long long)NB*NV){ chosen_f = outf; probs = outf + NB; }
    else {
        chosen_f = outf;
        if (osz >= (long long)NB + (long long)NB*NV) probs = outf + NB;
        if (osz >= fullN) nkv = outf + NB + (long long)NB*NV;
    }

    // side stream + events for the bulk kv copy (fresh per call; kernel_launch
    // is only invoked for the correctness run and the capture run, so the tiny
    // host-object leak is bounded and the captured graph is identical each time)
    cudaStream_t s2 = 0; cudaEvent_t evA = 0, evB = 0;
    if (nkv){
        cudaStreamCreateWithFlags(&s2, cudaStreamNonBlocking);
        cudaEventCreateWithFlags(&evA, cudaEventDisableTiming);
        cudaEventCreateWithFlags(&evB, cudaEventDisableTiming);
    }

    pdl_launch(embed_kernel, dim3(NB), dim3(256), ids, mask, wte, wpe);
    if (nkv){
        cudaEventRecord(evA, 0);
        cudaStreamWaitEvent(s2, evA, 0);
        kvcopy_kernel<<<(NL*2*NB*NS1)/8, 256, 0, s2>>>(kv, nkv);
        cudaEventRecord(evB, s2);
    }
    for (int l = 0; l < NL; l++){
        pdl_launch(gemv_ln_kernel<16>, dim3(3,48), dim3(256),
                   ln1w + l*NE, ln1b + l*NE,
                   caw + (size_t)l*NE*NE3, cab + (size_t)l*NE3, qkvp, NE3);
        pdl_launch(attn_kv_kernel, dim3(NB,128), dim3(256),
                   kv, ab + (size_t)l*NS1, mask, nkv, l);
        pdl_launch(attn_sv_kernel, dim3(NB,NH,16), dim3(256), kv, l);
        pdl_launch(gemv_kernel<8,0>, dim3(1,96), dim3(256),
                   (const float*)ctxp, cpw + (size_t)l*NE*NE, cpb + (size_t)l*NE,
                   st, NE, NE, qkvp, NB*NE3);
        pdl_launch(gemv_ln_kernel<16>, dim3(3,48), dim3(256),
                   ln2w + l*NE, ln2b + l*NE,
                   fcw + (size_t)l*NE*NFF, fcb + (size_t)l*NFF, hb, NFF);
        pdl_launch(gemv_kernel<16,1>, dim3(1,192), dim3(256),
                   (const float*)hb, prw + (size_t)l*NFF*NE, prb + (size_t)l*NE,
                   st, NFF, NE, ctxp, NB*NE);
    }
    pdl_launch(lm_kernel, dim3((NV + 15)/16), dim3(256), wte, lnfw, lnfb);
    pdl_launch(finish_kernel, dim3(NB), dim3(1024), probs, chosen_f, chosen_i);
    if (nkv){
        cudaStreamWaitEvent(0, evB, 0);   // join copy branch before graph end
    }
}

// round 13
// speedup vs baseline: 1.1970x; 1.1970x over previous
#include <cuda_runtime.h>
#include <math.h>

#define NB 8
#define NL 12
#define NS 1023
#define NS1 1024
#define NE 768
#define NH 12
#define ND 64
#define NV 50257
#define NFF 3072
#define NE3 2304

#define PDL_PROLOG  do { \
    asm volatile("griddepcontrol.launch_dependents;"); \
    asm volatile("griddepcontrol.wait;"); \
} while(0)

// ---------------- scratch (device globals) -------------------------------------
__device__ __align__(16) float g_states[NB*NE];
__device__ __align__(16) float g_qkv[NB*NE3];
__device__ __align__(16) float g_ctx[NB*NE];
__device__ __align__(16) float g_hbuf[NB*NFF];
__device__ __align__(16) float g_scores[NB*NH*NS1];
__device__ __align__(16) float g_logits[NB*NV];
__device__ int g_lp[NB];

// ---------------- embedding + last-position; zero qkv & ctx --------------------
__global__ void embed_kernel(const int* __restrict__ ids, const int* __restrict__ mask,
                             const float* __restrict__ wte, const float* __restrict__ wpe){
    PDL_PROLOG;
    int b = blockIdx.x, tid = threadIdx.x;
    __shared__ int s_lp;
    if (tid < 32){
        int best = -1;
        for (int s = tid; s < NS1; s += 32)
            if (mask[b*NS1 + s] != 0) best = (s > best) ? s : best;
        for (int o = 16; o; o >>= 1){
            int ot = __shfl_xor_sync(0xffffffffu, best, o);
            best = (ot > best) ? ot : best;
        }
        if (tid == 0){ s_lp = best; g_lp[b] = best; }
    }
    __syncthreads();
    int lp  = s_lp;
    int tok = ids[b*NS1 + lp];
    for (int e = tid; e < NE; e += blockDim.x)
        g_states[b*NE + e] = wte[(size_t)tok*NE + e] + wpe[(size_t)lp*NE + e];
    int g = b*256 + tid;
    for (int i = g; i < NB*NE3; i += NB*256) g_qkv[i] = 0.f;
    for (int i = g; i < NB*NE;  i += NB*256) g_ctx[i] = 0.f;
}

// ---------------- GEMV with fused redundant layernorm of g_states --------------
template<int CH>
__global__ void gemv_ln_kernel(const float* __restrict__ lnw, const float* __restrict__ lnb,
                               const float* __restrict__ W, const float* __restrict__ bias,
                               float* __restrict__ out, int N){
    PDL_PROLOG;
    __shared__ __align__(16) float xs[8*CH];
    int tid = threadIdx.x, warp = tid >> 5, lane = tid & 31;
    int e0 = blockIdx.y * CH;
    {   // LN of row `warp`
        const float* x = g_states + warp*NE;
        float s = 0.f;
        for (int i = lane; i < NE; i += 32) s += x[i];
        #pragma unroll
        for (int o = 16; o; o >>= 1) s += __shfl_xor_sync(0xffffffffu, s, o);
        float mean = s*(1.0f/NE);
        float v = 0.f;
        for (int i = lane; i < NE; i += 32){ float d = x[i]-mean; v += d*d; }
        #pragma unroll
        for (int o = 16; o; o >>= 1) v += __shfl_xor_sync(0xffffffffu, v, o);
        float rs = rsqrtf(v*(1.0f/NE) + 1e-5f);
        for (int i = lane; i < CH; i += 32){
            int e = e0 + i;
            xs[warp*CH + i] = (x[e]-mean)*rs*lnw[e] + lnb[e];
        }
    }
    __syncthreads();
    int j = (blockIdx.x*256 + tid)*4;
    if (j >= N) return;
    float4 acc[8];
    #pragma unroll
    for (int b2 = 0; b2 < 8; b2++) acc[b2] = make_float4(0.f,0.f,0.f,0.f);
    const float* Wp = W + (size_t)e0*N + j;
    #pragma unroll
    for (int e = 0; e < CH; e++){
        float4 w4 = __ldcs((const float4*)(Wp + (size_t)e*N));
        #pragma unroll
        for (int b2 = 0; b2 < 8; b2++){
            float xv = xs[b2*CH + e];
            acc[b2].x = fmaf(xv,w4.x,acc[b2].x); acc[b2].y = fmaf(xv,w4.y,acc[b2].y);
            acc[b2].z = fmaf(xv,w4.z,acc[b2].z); acc[b2].w = fmaf(xv,w4.w,acc[b2].w);
        }
    }
    if (blockIdx.y == 0){
        float4 bv = *(const float4*)(bias + j);
        #pragma unroll
        for (int b2 = 0; b2 < 8; b2++){
            acc[b2].x += bv.x; acc[b2].y += bv.y; acc[b2].z += bv.z; acc[b2].w += bv.w;
        }
    }
    #pragma unroll
    for (int b2 = 0; b2 < 8; b2++){
        float* p = out + (size_t)b2*N + j;
        atomicAdd(p+0,acc[b2].x); atomicAdd(p+1,acc[b2].y);
        atomicAdd(p+2,acc[b2].z); atomicAdd(p+3,acc[b2].w);
    }
}

// ---------------- plain GEMV (optional gelu) + optional buffer zeroing ---------
template<int CH, int DOGELU>
__global__ void gemv_kernel(const float* __restrict__ x, const float* __restrict__ W,
                            const float* __restrict__ bias, float* __restrict__ out,
                            int M, int N, float* zbuf, int zn){
    PDL_PROLOG;
    __shared__ __align__(16) float xs[8*CH];
    int tid = threadIdx.x;
    int e0 = blockIdx.y * CH;
    if (zbuf){
        int nb = gridDim.x*gridDim.y;
        for (int i = (blockIdx.y*gridDim.x + blockIdx.x)*256 + tid; i < zn; i += nb*256)
            zbuf[i] = 0.f;
    }
    for (int i = tid; i < 8*CH; i += 256){
        int b2 = i / CH, e = i - b2*CH;
        float v = x[b2*M + e0 + e];
        if (DOGELU) v = 0.5f*v*(1.0f + erff(v*0.70710678118654752f));
        xs[b2*CH + e] = v;
    }
    __syncthreads();
    int j = (blockIdx.x*256 + tid)*4;
    if (j >= N) return;
    float4 acc[8];
    #pragma unroll
    for (int b2 = 0; b2 < 8; b2++) acc[b2] = make_float4(0.f,0.f,0.f,0.f);
    const float* Wp = W + (size_t)e0*N + j;
    #pragma unroll
    for (int e = 0; e < CH; e++){
        float4 w4 = __ldcs((const float4*)(Wp + (size_t)e*N));
        #pragma unroll
        for (int b2 = 0; b2 < 8; b2++){
            float xv = xs[b2*CH + e];
            acc[b2].x = fmaf(xv,w4.x,acc[b2].x); acc[b2].y = fmaf(xv,w4.y,acc[b2].y);
            acc[b2].z = fmaf(xv,w4.z,acc[b2].z); acc[b2].w = fmaf(xv,w4.w,acc[b2].w);
        }
    }
    if (blockIdx.y == 0){
        float4 bv = *(const float4*)(bias + j);
        #pragma unroll
        for (int b2 = 0; b2 < 8; b2++){
            acc[b2].x += bv.x; acc[b2].y += bv.y; acc[b2].z += bv.z; acc[b2].w += bv.w;
        }
    }
    #pragma unroll
    for (int b2 = 0; b2 < 8; b2++){
        float* p = out + (size_t)b2*N + j;
        atomicAdd(p+0,acc[b2].x); atomicAdd(p+1,acc[b2].y);
        atomicAdd(p+2,acc[b2].z); atomicAdd(p+3,acc[b2].w);
    }
}

// ---------------- K+V copy into new_kv + attention scores; zero hbuf -----------
__global__ void attn_kv_kernel(const float* __restrict__ kv, const float* __restrict__ abias,
                               const int* __restrict__ mask, float* __restrict__ nkv, int l){
    PDL_PROLOG;
    int b = blockIdx.x, sc = blockIdx.y;
    int tid = threadIdx.x, warp = tid >> 5, lane = tid & 31;
    {
        for (int i = (b*128 + sc)*256 + tid; i < NB*NFF; i += NB*128*256) g_hbuf[i] = 0.f;
    }
    __shared__ __align__(16) float qs[NE];
    for (int i = tid; i < NE; i += 256) qs[i] = g_qkv[b*NE3 + i];
    __syncthreads();
    int lp = g_lp[b];
    const float* kc = kv + ((size_t)(l*2+0)*NB + b)*(size_t)NS*NE;
    const float* vc = kv + ((size_t)(l*2+1)*NB + b)*(size_t)NS*NE;
    float* ko = nkv ? nkv + ((size_t)(l*2+0)*NB + b)*(size_t)NS1*NE : nullptr;
    float* vo = nkv ? nkv + ((size_t)(l*2+1)*NB + b)*(size_t)NS1*NE : nullptr;
    int s = sc*8 + warp;
    bool isnew = (s == lp);
    bool iszero = (s == NS) && !isnew;
    const float* ksrc = isnew ? (g_qkv + b*NE3 + NE)   : (kc + (size_t)s*NE);
    const float* vsrc = isnew ? (g_qkv + b*NE3 + 2*NE) : (vc + (size_t)s*NE);
    float4 k4[6], v4[6];
    #pragma unroll
    for (int c = 0; c < 6; c++){
        int e = c*128 + lane*4;
        if (iszero){ k4[c] = make_float4(0.f,0.f,0.f,0.f); v4[c] = k4[c]; }
        else { k4[c] = *(const float4*)(ksrc + e); v4[c] = *(const float4*)(vsrc + e); }
    }
    if (ko){
        #pragma unroll
        for (int c = 0; c < 6; c++){
            int e = c*128 + lane*4;
            __stcs((float4*)(ko + (size_t)s*NE + e), k4[c]);     // K never re-read
            *(float4*)(vo + (size_t)s*NE + e) = v4[c];           // V re-read by attn_sv
        }
    }
    float part[6];
    #pragma unroll
    for (int c = 0; c < 6; c++){
        int e = c*128 + lane*4;
        part[c] = k4[c].x*qs[e] + k4[c].y*qs[e+1] + k4[c].z*qs[e+2] + k4[c].w*qs[e+3];
    }
    #pragma unroll
    for (int c = 0; c < 6; c++){
        float p = part[c];
        p += __shfl_xor_sync(0xffffffffu, p, 8);
        p += __shfl_xor_sync(0xffffffffu, p, 4);
        p += __shfl_xor_sync(0xffffffffu, p, 2);
        p += __shfl_xor_sync(0xffffffffu, p, 1);
        part[c] = p;
    }
    if ((lane & 15) == 0){
        int hb = lane >> 4;
        bool msk = (mask[b*NS1 + s] == 0);
        float ab = abias[s];
        #pragma unroll
        for (int c = 0; c < 6; c++){
            int h = 2*c + hb;
            g_scores[(b*NH + h)*NS1 + s] = msk ? -1e9f : (part[c]*0.125f + ab);
        }
    }
}

// ---------------- softmax + weighted-V -----------------------------------------
// grid (B, H, 16) x 256: block = one (b,h) x 64-row chunk; redundant softmax.
// Masked rows have sm == 0.0f exactly -> warp-uniform skip of the V load.
__global__ void attn_sv_kernel(const float* __restrict__ kv, const float* __restrict__ nkv, int l){
    PDL_PROLOG;
    int b = blockIdx.x, h = blockIdx.y, ck = blockIdx.z;
    int tid = threadIdx.x;
    __shared__ float sm[NS1];
    __shared__ float red[8];
    const float* sr = g_scores + ((size_t)b*NH + h)*NS1;
    float v[4]; float m = -1e30f;
    #pragma unroll
    for (int k = 0; k < 4; k++){ v[k] = sr[tid + k*256]; m = fmaxf(m, v[k]); }
    #pragma unroll
    for (int o = 16; o; o >>= 1) m = fmaxf(m, __shfl_xor_sync(0xffffffffu, m, o));
    if ((tid & 31) == 0) red[tid >> 5] = m;
    __syncthreads();
    m = red[0];
    #pragma unroll
    for (int w2 = 1; w2 < 8; w2++) m = fmaxf(m, red[w2]);
    float ssum = 0.f;
    #pragma unroll
    for (int k = 0; k < 4; k++){ v[k] = expf(v[k] - m); ssum += v[k]; }
    #pragma unroll
    for (int o = 16; o; o >>= 1) ssum += __shfl_xor_sync(0xffffffffu, ssum, o);
    __syncthreads();
    if ((tid & 31) == 0) red[tid >> 5] = ssum;
    __syncthreads();
    float tot = red[0];
    #pragma unroll
    for (int w2 = 1; w2 < 8; w2++) tot += red[w2];
    float inv = 1.0f/tot;
    #pragma unroll
    for (int k = 0; k < 4; k++) sm[tid + k*256] = v[k]*inv;
    __syncthreads();
    int col = tid & 63, rp = tid >> 6;          // rp in 0..3; s uniform per warp
    float acc = 0.f;
    if (nkv){
        const float* vo = nkv + ((size_t)(l*2+1)*NB + b)*(size_t)NS1*NE + h*ND + col;
        #pragma unroll
        for (int i = 0; i < 16; i++){
            int s = ck*64 + i*4 + rp;
            float w = sm[s];
            if (w != 0.f)                        // warp-uniform: skip masked rows
                acc = fmaf(w, vo[(size_t)s*NE], acc);
        }
    } else {
        int lp = g_lp[b];
        const float* vc = kv + ((size_t)(l*2+1)*NB + b)*(size_t)NS*NE;
        #pragma unroll
        for (int i = 0; i < 16; i++){
            int s = ck*64 + i*4 + rp;
            float w = sm[s];
            if (w != 0.f){
                float vv;
                if (s == lp) vv = g_qkv[b*NE3 + 2*NE + h*ND + col];
                else if (s == NS) vv = 0.f;
                else vv = vc[(size_t)s*NE + h*ND + col];
                acc = fmaf(w, vv, acc);
            }
        }
    }
    __shared__ float cacc[256];
    cacc[tid] = acc; __syncthreads();
    if (tid < 64)
        atomicAdd(&g_ctx[b*NE + h*ND + tid],
                  cacc[tid] + cacc[tid+64] + cacc[tid+128] + cacc[tid+192]);
}

// ---------------- lm head with fused final layernorm ---------------------------
__global__ void lm_kernel(const float* __restrict__ wte, const float* __restrict__ lnfw,
                          const float* __restrict__ lnfb){
    PDL_PROLOG;
    __shared__ __align__(16) float xs[NB*NE];
    int tid = threadIdx.x;
    int warp = tid >> 5, lane = tid & 31;
    {   // redundant LN of row `warp` (8 warps = 8 batch rows)
        const float* x = g_states + warp*NE;
        float s = 0.f;
        for (int i = lane; i < NE; i += 32) s += x[i];
        #pragma unroll
        for (int o = 16; o; o >>= 1) s += __shfl_xor_sync(0xffffffffu, s, o);
        float mean = s*(1.0f/NE);
        float v = 0.f;
        for (int i = lane; i < NE; i += 32){ float d = x[i]-mean; v += d*d; }
        #pragma unroll
        for (int o = 16; o; o >>= 1) v += __shfl_xor_sync(0xffffffffu, v, o);
        float rs = rsqrtf(v*(1.0f/NE) + 1e-5f);
        for (int i = lane; i < NE; i += 32)
            xs[warp*NE + i] = (x[i]-mean)*rs*lnfw[i] + lnfb[i];
    }
    __syncthreads();
    long long t0 = (long long)blockIdx.x*16 + warp*2;
    if (t0 >= NV) return;
    bool has1 = (t0 + 1 < NV);
    const float* r0 = wte + (size_t)t0*NE;
    const float* r1 = has1 ? wte + (size_t)(t0+1)*NE : r0;
    float acc[16];
    #pragma unroll
    for (int i = 0; i < 16; i++) acc[i] = 0.f;
    #pragma unroll
    for (int c = 0; c < 6; c++){
        int e = c*128 + lane*4;
        float4 w0 = __ldcs((const float4*)(r0 + e));
        float4 w1 = __ldcs((const float4*)(r1 + e));
        #pragma unroll
        for (int b2 = 0; b2 < 8; b2++){
            float4 x4 = *(const float4*)&xs[b2*NE + e];
            acc[b2]   = fmaf(w0.x,x4.x, fmaf(w0.y,x4.y, fmaf(w0.z,x4.z, fmaf(w0.w,x4.w, acc[b2]))));
            acc[8+b2] = fmaf(w1.x,x4.x, fmaf(w1.y,x4.y, fmaf(w1.z,x4.z, fmaf(w1.w,x4.w, acc[8+b2]))));
        }
    }
    #pragma unroll
    for (int i = 0; i < 16; i++){
        float p = acc[i];
        p += __shfl_xor_sync(0xffffffffu, p, 16);
        p += __shfl_xor_sync(0xffffffffu, p, 8);
        p += __shfl_xor_sync(0xffffffffu, p, 4);
        p += __shfl_xor_sync(0xffffffffu, p, 2);
        p += __shfl_xor_sync(0xffffffffu, p, 1);
        acc[i] = p;
    }
    if (lane < 8){
        g_logits[(size_t)lane*NV + t0] = acc[lane];
        if (has1) g_logits[(size_t)lane*NV + t0 + 1] = acc[8 + lane];
    }
}

// ---------------- vocab softmax + argmax (ILP-4 loops) -------------------------
__global__ void finish_kernel(float* __restrict__ probs, float* __restrict__ chosen_f,
                              int* __restrict__ chosen_i){
    PDL_PROLOG;
    int b = blockIdx.x, tid = threadIdx.x;
    __shared__ float rv[1024];
    __shared__ int   ri[1024];
    const float* lg = g_logits + (size_t)b*NV;
    float m = -1e30f; int mi = 0;
    for (int t = tid; t < NV; t += 4096){
        float v0 = lg[t];
        float v1 = (t+1024 < NV) ? lg[t+1024] : -1e30f;
        float v2 = (t+2048 < NV) ? lg[t+2048] : -1e30f;
        float v3 = (t+3072 < NV) ? lg[t+3072] : -1e30f;
        if (v0 > m){ m = v0; mi = t; }
        if (v1 > m){ m = v1; mi = t+1024; }
        if (v2 > m){ m = v2; mi = t+2048; }
        if (v3 > m){ m = v3; mi = t+3072; }
    }
    rv[tid] = m; ri[tid] = mi; __syncthreads();
    for (int o = 512; o; o >>= 1){
        if (tid < o){
            if (rv[tid+o] > rv[tid] || (rv[tid+o] == rv[tid] && ri[tid+o] < ri[tid])){
                rv[tid] = rv[tid+o]; ri[tid] = ri[tid+o];
            }
        }
        __syncthreads();
    }
    float mx = rv[0]; int am = ri[0]; __syncthreads();
    float s = 0.f;
    for (int t = tid; t < NV; t += 4096){
        float v0 = lg[t];
        float v1 = (t+1024 < NV) ? lg[t+1024] : 0.f;
        float v2 = (t+2048 < NV) ? lg[t+2048] : 0.f;
        float v3 = (t+3072 < NV) ? lg[t+3072] : 0.f;
        float e0 = expf(v0-mx);
        float e1 = (t+1024 < NV) ? expf(v1-mx) : 0.f;
        float e2 = (t+2048 < NV) ? expf(v2-mx) : 0.f;
        float e3 = (t+3072 < NV) ? expf(v3-mx) : 0.f;
        s += (e0+e1)+(e2+e3);
        if (probs){
            probs[(size_t)b*NV + t] = e0;
            if (t+1024 < NV) probs[(size_t)b*NV + t+1024] = e1;
            if (t+2048 < NV) probs[(size_t)b*NV + t+2048] = e2;
            if (t+3072 < NV) probs[(size_t)b*NV + t+3072] = e3;
        }
    }
    rv[tid] = s; __syncthreads();
    for (int o = 512; o; o >>= 1){ if (tid < o) rv[tid] += rv[tid+o]; __syncthreads(); }
    float inv = 1.0f/rv[0];
    if (probs){
        float* pb = probs + (size_t)b*NV;
        for (int t = tid; t < NV; t += 4096){
            float p0 = pb[t];
            float p1 = (t+1024 < NV) ? pb[t+1024] : 0.f;
            float p2 = (t+2048 < NV) ? pb[t+2048] : 0.f;
            float p3 = (t+3072 < NV) ? pb[t+3072] : 0.f;
            pb[t] = p0*inv;
            if (t+1024 < NV) pb[t+1024] = p1*inv;
            if (t+2048 < NV) pb[t+2048] = p2*inv;
            if (t+3072 < NV) pb[t+3072] = p3*inv;
        }
    }
    if (tid == 0){
        if (chosen_f) chosen_f[b] = (float)am;
        if (chosen_i) chosen_i[b] = am;
    }
}

// ---------------- PDL launch helper ---------------------------------------------
template <typename... ExpTypes, typename... ActTypes>
static inline void pdl_launch(void (*kern)(ExpTypes...), dim3 grid, dim3 block,
                              ActTypes... args){
    cudaLaunchConfig_t cfg = {};
    cfg.gridDim = grid;
    cfg.blockDim = block;
    cfg.dynamicSmemBytes = 0;
    cfg.stream = 0;
    cudaLaunchAttribute at[1];
    at[0].id = cudaLaunchAttributeProgrammaticStreamSerialization;
    at[0].val.programmaticStreamSerializationAllowed = 1;
    cfg.attrs = at;
    cfg.numAttrs = 1;
    cudaLaunchKernelEx(&cfg, kern, (ExpTypes)args...);
}

// ---------------- launch --------------------------------------------------------
extern "C" void kernel_launch(void* const* d_in, const int* in_sizes, int n_in,
                              void* d_out, int out_size){
    const int*   ids  = (const int*)  d_in[0];
    const int*   mask = (const int*)  d_in[1];
    const float* kv   = (const float*)d_in[2];
    const float* wte  = (const float*)d_in[3];
    const float* wpe  = (const float*)d_in[4];
    const float* ln1w = (const float*)d_in[5];
    const float* ln1b = (const float*)d_in[6];
    const float* caw  = (const float*)d_in[7];
    const float* cab  = (const float*)d_in[8];
    const float* ab   = (const float*)d_in[9];
    const float* cpw  = (const float*)d_in[10];
    const float* cpb  = (const float*)d_in[11];
    const float* ln2w = (const float*)d_in[12];
    const float* ln2b = (const float*)d_in[13];
    const float* fcw  = (const float*)d_in[14];
    const float* fcb  = (const float*)d_in[15];
    const float* prw  = (const float*)d_in[16];
    const float* prb  = (const float*)d_in[17];
    const float* lnfw = (const float*)d_in[18];
    const float* lnfb = (const float*)d_in[19];

    float *st, *qkvp, *ctxp, *hb;
    cudaGetSymbolAddress((void**)&st,   g_states);
    cudaGetSymbolAddress((void**)&qkvp, g_qkv);
    cudaGetSymbolAddress((void**)&ctxp, g_ctx);
    cudaGetSymbolAddress((void**)&hb,   g_hbuf);

    long long nkvN  = (long long)NL*2*NB*NS1*NE;                  // 150,994,944
    long long fullN = (long long)NB + (long long)NB*NV + nkvN;    // 151,397,008
    float* outf = (float*)d_out;
    float* chosen_f = nullptr; int* chosen_i = nullptr;
    float* probs = nullptr; float* nkv = nullptr;
    long long osz = (long long)out_size;
    if (osz == fullN){ chosen_f = outf; probs = outf + NB; nkv = outf + NB + (long long)NB*NV; }
    else if (osz == nkvN){ nkv = outf; }
    else if (osz == (long long)NB*NV){ probs = outf; }
    else if (osz == (long long)NB){ chosen_i = (int*)d_out; }
    else if (osz == (long long)NB + (long long)NB*NV){ chosen_f = outf; probs = outf + NB; }
    else {
        chosen_f = outf;
        if (osz >= (long long)NB + (long long)NB*NV) probs = outf + NB;
        if (osz >= fullN) nkv = outf + NB + (long long)NB*NV;
    }

    pdl_launch(embed_kernel, dim3(NB), dim3(256), ids, mask, wte, wpe);
    for (int l = 0; l < NL; l++){
        pdl_launch(gemv_ln_kernel<16>, dim3(3,48), dim3(256),
                   ln1w + l*NE, ln1b + l*NE,
                   caw + (size_t)l*NE*NE3, cab + (size_t)l*NE3, qkvp, NE3);
        pdl_launch(attn_kv_kernel, dim3(NB,128), dim3(256),
                   kv, ab + (size_t)l*NS1, mask, nkv, l);
        pdl_launch(attn_sv_kernel, dim3(NB,NH,16), dim3(256), kv, (const float*)nkv, l);
        pdl_launch(gemv_kernel<16,0>, dim3(1,48), dim3(256),
                   (const float*)ctxp, cpw + (size_t)l*NE*NE, cpb + (size_t)l*NE,
                   st, NE, NE, qkvp, NB*NE3);
        pdl_launch(gemv_ln_kernel<16>, dim3(3,48), dim3(256),
                   ln2w + l*NE, ln2b + l*NE,
                   fcw + (size_t)l*NE*NFF, fcb + (size_t)l*NFF, hb, NFF);
        pdl_launch(gemv_kernel<24,1>, dim3(1,128), dim3(256),
                   (const float*)hb, prw + (size_t)l*NFF*NE, prb + (size_t)l*NE,
                   st, NFF, NE, ctxp, NB*NE);
    }
    pdl_launch(lm_kernel, dim3((NV + 15)/16), dim3(256), wte, lnfw, lnfb);
    pdl_launch(finish_kernel, dim3(NB), dim3(1024), probs, chosen_f, chosen_i);
}